// round 1
// baseline (speedup 1.0000x reference)
#include <cuda_runtime.h>
#include <cuda_bf16.h>
#include <math.h>

#define Nn 20000
#define Ee 320000
#define Ff 64
#define Hh 256
#define Cc 10
#define Gg 64

// ---------------- device scratch (static, no allocation) ----------------
__device__ float g_bufA[Nn * Hh];   // XW (GEMM output)
__device__ float g_bufB[Nn * Hh];   // aggregated hidden state
__device__ float g_dinv[Nn];
__device__ int   g_cnt[Nn];         // in-degree counts (excl self loop)
__device__ int   g_off[Nn + 1];     // CSR offsets
__device__ int   g_cur[Nn];         // scatter cursors
__device__ int   g_csr[Ee];         // source node per (dest-sorted) edge
__device__ float g_pool[Gg * Hh];
__device__ int   g_pcnt[Gg];

// ---------------- init: zero counters/accumulators ----------------
__global__ void init_kernel() {
    int idx = blockIdx.x * blockDim.x + threadIdx.x;
    if (idx < Nn) g_cnt[idx] = 0;
    if (idx < Gg * Hh) g_pool[idx] = 0.0f;
    if (idx < Gg) g_pcnt[idx] = 0;
}

// ---------------- degree count over destination (col) ----------------
__global__ void deg_kernel(const int* __restrict__ edge_index) {
    int e = blockIdx.x * blockDim.x + threadIdx.x;
    if (e < Ee) {
        int c = edge_index[Ee + e];   // col = edge_index[1]
        atomicAdd(&g_cnt[c], 1);
    }
}

// ---------------- single-block scan: offsets, cursors, dinv ----------------
#define SCAN_T 1024
#define SCAN_CH ((Nn + SCAN_T - 1) / SCAN_T)
__global__ void scan_kernel() {
    __shared__ int sh[SCAN_T];
    int t = threadIdx.x;
    int base = t * SCAN_CH;
    int s = 0;
    #pragma unroll
    for (int i = 0; i < SCAN_CH; i++) {
        int idx = base + i;
        if (idx < Nn) s += g_cnt[idx];
    }
    sh[t] = s;
    __syncthreads();
    for (int d = 1; d < SCAN_T; d <<= 1) {
        int v = (t >= d) ? sh[t - d] : 0;
        __syncthreads();
        sh[t] += v;
        __syncthreads();
    }
    int run = (t == 0) ? 0 : sh[t - 1];
    for (int i = 0; i < SCAN_CH; i++) {
        int idx = base + i;
        if (idx < Nn) {
            int c = g_cnt[idx];
            g_off[idx] = run;
            g_cur[idx] = run;
            g_dinv[idx] = rsqrtf((float)(c + 1));   // +1 self loop
            run += c;
        }
    }
    if (t == SCAN_T - 1) g_off[Nn] = sh[SCAN_T - 1];
}

// ---------------- scatter edges into dest-sorted CSR ----------------
__global__ void scatter_kernel(const int* __restrict__ edge_index) {
    int e = blockIdx.x * blockDim.x + threadIdx.x;
    if (e < Ee) {
        int r = edge_index[e];        // row = src
        int c = edge_index[Ee + e];   // col = dst
        int p = atomicAdd(&g_cur[c], 1);
        g_csr[p] = r;
    }
}

// ---------------- tiled fp32 GEMM: out[n,M] = A[n,K] @ W[K,M] ----------------
// BM=BN=64, BK=16, 256 threads, 4x4 micro-tile per thread. M == 256.
__device__ __forceinline__ void gemm_body(const float* __restrict__ A,
                                          const float* __restrict__ W,
                                          float* __restrict__ out,
                                          int n, int K, int M) {
    __shared__ float As[16][65];
    __shared__ float Bs[16][64];
    int tid = threadIdx.x;
    int tr = tid >> 4;          // 0..15
    int tc = tid & 15;          // 0..15
    int row0 = blockIdx.y * 64;
    int col0 = blockIdx.x * 64;

    float acc[4][4];
    #pragma unroll
    for (int i = 0; i < 4; i++)
        #pragma unroll
        for (int j = 0; j < 4; j++) acc[i][j] = 0.0f;

    for (int k0 = 0; k0 < K; k0 += 16) {
        // load A tile 64x16 (row-major source)
        #pragma unroll
        for (int l = 0; l < 4; l++) {
            int idx = tid + l * 256;        // 0..1023
            int rr = idx >> 4;              // 0..63
            int kk = idx & 15;              // 0..15
            float v = 0.0f;
            int gr = row0 + rr;
            if (gr < n) v = A[gr * K + k0 + kk];
            As[kk][rr] = v;
        }
        // load W tile 16x64
        #pragma unroll
        for (int l = 0; l < 4; l++) {
            int idx = tid + l * 256;
            int cc = idx & 63;
            int kk = idx >> 6;              // 0..15
            Bs[kk][cc] = W[(k0 + kk) * M + col0 + cc];
        }
        __syncthreads();
        #pragma unroll
        for (int k = 0; k < 16; k++) {
            float a[4], b[4];
            #pragma unroll
            for (int i = 0; i < 4; i++) a[i] = As[k][tr * 4 + i];
            #pragma unroll
            for (int j = 0; j < 4; j++) b[j] = Bs[k][tc * 4 + j];
            #pragma unroll
            for (int i = 0; i < 4; i++)
                #pragma unroll
                for (int j = 0; j < 4; j++)
                    acc[i][j] = fmaf(a[i], b[j], acc[i][j]);
        }
        __syncthreads();
    }
    #pragma unroll
    for (int i = 0; i < 4; i++) {
        int gr = row0 + tr * 4 + i;
        if (gr < n) {
            #pragma unroll
            for (int j = 0; j < 4; j++)
                out[gr * M + col0 + tc * 4 + j] = acc[i][j];
        }
    }
}

__global__ void gemm_x_kernel(const float* __restrict__ x,
                              const float* __restrict__ W) {
    gemm_body(x, W, g_bufA, Nn, Ff, Hh);
}
__global__ void gemm_h_kernel(const float* __restrict__ W) {
    gemm_body(g_bufB, W, g_bufA, Nn, Hh, Hh);
}

// ---------------- aggregation: bufB[i] = relu( dinv-normalized sum + b ) ----
__global__ void agg_kernel(const float* __restrict__ b) {
    int i = blockIdx.x;
    int f = threadIdx.x;    // 0..255
    float di = g_dinv[i];
    float self = g_bufA[i * Hh + f];
    int s = g_off[i];
    int e = g_off[i + 1];
    float acc0 = 0.0f, acc1 = 0.0f;
    int k = s;
    for (; k + 2 <= e; k += 2) {
        int j0 = g_csr[k];
        int j1 = g_csr[k + 1];
        float w0 = g_dinv[j0];
        float w1 = g_dinv[j1];
        float v0 = g_bufA[j0 * Hh + f];
        float v1 = g_bufA[j1 * Hh + f];
        acc0 = fmaf(w0, v0, acc0);
        acc1 = fmaf(w1, v1, acc1);
    }
    if (k < e) {
        int j0 = g_csr[k];
        acc0 = fmaf(g_dinv[j0], g_bufA[j0 * Hh + f], acc0);
    }
    float val = di * (di * self + acc0 + acc1) + b[f];
    g_bufB[i * Hh + f] = fmaxf(val, 0.0f);
}

// ---------------- pooling: per-graph sums ----------------
__global__ void pool_kernel(const int* __restrict__ batch) {
    int i = blockIdx.x;
    int f = threadIdx.x;
    int g = batch[i];
    atomicAdd(&g_pool[g * Hh + f], g_bufB[i * Hh + f]);
    if (f == 0) atomicAdd(&g_pcnt[g], 1);
}

// ---------------- output: mean + Wout ----------------
__global__ void out_kernel(const float* __restrict__ Wout,
                           const float* __restrict__ bout,
                           float* __restrict__ out) {
    __shared__ float sh[Hh];
    int g = blockIdx.x;
    int f = threadIdx.x;
    int c = g_pcnt[g];
    float inv = 1.0f / fmaxf((float)c, 1.0f);
    sh[f] = g_pool[g * Hh + f] * inv;
    __syncthreads();
    if (f < Cc) {
        float a = bout[f];
        for (int k = 0; k < Hh; k++)
            a = fmaf(sh[k], Wout[k * Cc + f], a);
        out[g * Cc + f] = a;
    }
}

// ---------------- launch ----------------
extern "C" void kernel_launch(void* const* d_in, const int* in_sizes, int n_in,
                              void* d_out, int out_size) {
    const float* x     = (const float*)d_in[0];
    const int*   ei    = (const int*)d_in[1];
    const int*   batch = (const int*)d_in[2];
    const float* W1 = (const float*)d_in[3];
    const float* b1 = (const float*)d_in[4];
    const float* W2 = (const float*)d_in[5];
    const float* b2 = (const float*)d_in[6];
    const float* W3 = (const float*)d_in[7];
    const float* b3 = (const float*)d_in[8];
    const float* W4 = (const float*)d_in[9];
    const float* b4 = (const float*)d_in[10];
    const float* W5 = (const float*)d_in[11];
    const float* b5 = (const float*)d_in[12];
    const float* Wout = (const float*)d_in[13];
    const float* bout = (const float*)d_in[14];
    float* out = (float*)d_out;

    dim3 ggrid(Hh / 64, (Nn + 63) / 64);   // (4, 313)
    int eblocks = (Ee + 255) / 256;

    init_kernel<<<(Nn + 255) / 256, 256>>>();
    deg_kernel<<<eblocks, 256>>>(ei);
    scan_kernel<<<1, SCAN_T>>>();
    scatter_kernel<<<eblocks, 256>>>(ei);

    // layer 1 (input F=64)
    gemm_x_kernel<<<ggrid, 256>>>(x, W1);
    agg_kernel<<<Nn, 256>>>(b1);
    // layers 2..5
    gemm_h_kernel<<<ggrid, 256>>>(W2);
    agg_kernel<<<Nn, 256>>>(b2);
    gemm_h_kernel<<<ggrid, 256>>>(W3);
    agg_kernel<<<Nn, 256>>>(b3);
    gemm_h_kernel<<<ggrid, 256>>>(W4);
    agg_kernel<<<Nn, 256>>>(b4);
    gemm_h_kernel<<<ggrid, 256>>>(W5);
    agg_kernel<<<Nn, 256>>>(b5);

    pool_kernel<<<Nn, 256>>>(batch);
    out_kernel<<<Gg, 256>>>(Wout, bout, out);
}

// round 2
// speedup vs baseline: 1.6938x; 1.6938x over previous
#include <cuda_runtime.h>
#include <cuda_fp16.h>
#include <math.h>
#include <stdint.h>

#define Nn 20000
#define Ee 320000
#define Ff 64
#define Hh 256
#define Cc 10
#define Gg 64

// ---------------- device scratch (static, no allocation) ----------------
__device__ float  g_z[Nn * Hh];          // GEMM output (pre-aggregation), fp32
__device__ __half g_hi[Nn * Hh];         // hidden state hi (fp16)
__device__ __half g_lo[Nn * Hh];         // hidden state lo (fp16)
__device__ __half g_xhi[Nn * Ff];        // aggregated X hi
__device__ __half g_xlo[Nn * Ff];        // aggregated X lo
__device__ __half g_whiT[4 * Hh * Hh];   // W2..W5 transposed [m][k], hi
__device__ __half g_wloT[4 * Hh * Hh];   // W2..W5 transposed [m][k], lo
__device__ __half g_w1hiT[Hh * Ff];      // W1 transposed [m=256][k=64]
__device__ __half g_w1loT[Hh * Ff];

__device__ float g_dinv[Nn];
__device__ int   g_cnt[Nn];
__device__ int   g_off[Nn + 1];
__device__ int   g_cur[Nn];
__device__ int   g_csr[Ee];
__device__ float g_pool[Gg * Hh];
__device__ int   g_pcnt[Gg];

// ---------------- init ----------------
__global__ void init_kernel() {
    int idx = blockIdx.x * blockDim.x + threadIdx.x;
    if (idx < Nn) g_cnt[idx] = 0;
    if (idx < Gg * Hh) g_pool[idx] = 0.0f;
    if (idx < Gg) g_pcnt[idx] = 0;
}

// ---------------- degree count over destination ----------------
__global__ void deg_kernel(const int* __restrict__ edge_index) {
    int e = blockIdx.x * blockDim.x + threadIdx.x;
    if (e < Ee) atomicAdd(&g_cnt[edge_index[Ee + e]], 1);
}

// ---------------- single-block scan ----------------
#define SCAN_T 1024
#define SCAN_CH ((Nn + SCAN_T - 1) / SCAN_T)
__global__ void scan_kernel() {
    __shared__ int sh[SCAN_T];
    int t = threadIdx.x;
    int base = t * SCAN_CH;
    int s = 0;
    #pragma unroll
    for (int i = 0; i < SCAN_CH; i++) {
        int idx = base + i;
        if (idx < Nn) s += g_cnt[idx];
    }
    sh[t] = s;
    __syncthreads();
    for (int d = 1; d < SCAN_T; d <<= 1) {
        int v = (t >= d) ? sh[t - d] : 0;
        __syncthreads();
        sh[t] += v;
        __syncthreads();
    }
    int run = (t == 0) ? 0 : sh[t - 1];
    for (int i = 0; i < SCAN_CH; i++) {
        int idx = base + i;
        if (idx < Nn) {
            int c = g_cnt[idx];
            g_off[idx] = run;
            g_cur[idx] = run;
            g_dinv[idx] = rsqrtf((float)(c + 1));
            run += c;
        }
    }
    if (t == SCAN_T - 1) g_off[Nn] = sh[SCAN_T - 1];
}

// ---------------- scatter into dest-sorted CSR ----------------
__global__ void scatter_kernel(const int* __restrict__ edge_index) {
    int e = blockIdx.x * blockDim.x + threadIdx.x;
    if (e < Ee) {
        int r = edge_index[e];
        int c = edge_index[Ee + e];
        g_csr[atomicAdd(&g_cur[c], 1)] = r;
    }
}

// ---------------- weight prep: split fp32 -> (hi,lo) fp16, transpose to [m][k]
__global__ void wprep_kernel(const float* __restrict__ W, int widx, int K) {
    int idx = blockIdx.x * blockDim.x + threadIdx.x;
    if (idx >= K * Hh) return;
    int m = idx / K;
    int k = idx - m * K;
    float v = W[k * Hh + m];
    __half hi = __float2half_rn(v);
    __half lo = __float2half_rn(v - __half2float(hi));
    if (widx < 0) { g_w1hiT[idx] = hi; g_w1loT[idx] = lo; }
    else { g_whiT[widx * Hh * Hh + idx] = hi; g_wloT[widx * Hh * Hh + idx] = lo; }
}

// ---------------- aggregate raw X (F=64), write fp16 hi/lo ----------------
// out[i] = dinv_i * ( dinv_i * x_i + sum_j dinv_j * x_j )
__global__ void aggx_kernel(const float* __restrict__ x) {
    int tid = threadIdx.x;
    int node = blockIdx.x * 16 + (tid >> 4);   // 1250 blocks * 16 nodes
    int lane = tid & 15;                       // feature group (4 floats)
    float di = g_dinv[node];
    const float4* x4 = (const float4*)x;
    float4 self = x4[node * 16 + lane];
    float4 acc;
    acc.x = di * self.x; acc.y = di * self.y; acc.z = di * self.z; acc.w = di * self.w;
    int s = g_off[node], e = g_off[node + 1];
    int k = s;
    for (; k + 2 <= e; k += 2) {
        int j0 = g_csr[k], j1 = g_csr[k + 1];
        float w0 = g_dinv[j0], w1 = g_dinv[j1];
        float4 v0 = x4[j0 * 16 + lane];
        float4 v1 = x4[j1 * 16 + lane];
        acc.x = fmaf(w0, v0.x, acc.x); acc.y = fmaf(w0, v0.y, acc.y);
        acc.z = fmaf(w0, v0.z, acc.z); acc.w = fmaf(w0, v0.w, acc.w);
        acc.x = fmaf(w1, v1.x, acc.x); acc.y = fmaf(w1, v1.y, acc.y);
        acc.z = fmaf(w1, v1.z, acc.z); acc.w = fmaf(w1, v1.w, acc.w);
    }
    if (k < e) {
        int j0 = g_csr[k];
        float w0 = g_dinv[j0];
        float4 v0 = x4[j0 * 16 + lane];
        acc.x = fmaf(w0, v0.x, acc.x); acc.y = fmaf(w0, v0.y, acc.y);
        acc.z = fmaf(w0, v0.z, acc.z); acc.w = fmaf(w0, v0.w, acc.w);
    }
    float r0 = di * acc.x, r1 = di * acc.y, r2 = di * acc.z, r3 = di * acc.w;
    __half h0 = __float2half_rn(r0), h1 = __float2half_rn(r1);
    __half h2 = __float2half_rn(r2), h3 = __float2half_rn(r3);
    __half l0 = __float2half_rn(r0 - __half2float(h0));
    __half l1 = __float2half_rn(r1 - __half2float(h1));
    __half l2 = __float2half_rn(r2 - __half2float(h2));
    __half l3 = __float2half_rn(r3 - __half2float(h3));
    int off = node * Ff + lane * 4;
    *(__half2*)(g_xhi + off)     = __halves2half2(h0, h1);
    *(__half2*)(g_xhi + off + 2) = __halves2half2(h2, h3);
    *(__half2*)(g_xlo + off)     = __halves2half2(l0, l1);
    *(__half2*)(g_xlo + off + 2) = __halves2half2(l2, l3);
}

// ---------------- aggregation for layers 2..5 (reads g_z fp32) ----------
// h[i] = relu( dinv_i*(dinv_i*z_i + sum_j dinv_j*z_j) + b ), stored hi/lo fp16
__global__ void agg_kernel(const float* __restrict__ b) {
    int tid = threadIdx.x;
    int node = blockIdx.x * 4 + (tid >> 6);    // 5000 blocks * 4 nodes
    int lane = tid & 63;                       // feature group (4 floats)
    float di = g_dinv[node];
    const float4* z4 = (const float4*)g_z;
    float4 self = z4[node * 64 + lane];
    float4 acc;
    acc.x = di * self.x; acc.y = di * self.y; acc.z = di * self.z; acc.w = di * self.w;
    int s = g_off[node], e = g_off[node + 1];
    int k = s;
    for (; k + 2 <= e; k += 2) {
        int j0 = g_csr[k], j1 = g_csr[k + 1];
        float w0 = g_dinv[j0], w1 = g_dinv[j1];
        float4 v0 = z4[j0 * 64 + lane];
        float4 v1 = z4[j1 * 64 + lane];
        acc.x = fmaf(w0, v0.x, acc.x); acc.y = fmaf(w0, v0.y, acc.y);
        acc.z = fmaf(w0, v0.z, acc.z); acc.w = fmaf(w0, v0.w, acc.w);
        acc.x = fmaf(w1, v1.x, acc.x); acc.y = fmaf(w1, v1.y, acc.y);
        acc.z = fmaf(w1, v1.z, acc.z); acc.w = fmaf(w1, v1.w, acc.w);
    }
    if (k < e) {
        int j0 = g_csr[k];
        float w0 = g_dinv[j0];
        float4 v0 = z4[j0 * 64 + lane];
        acc.x = fmaf(w0, v0.x, acc.x); acc.y = fmaf(w0, v0.y, acc.y);
        acc.z = fmaf(w0, v0.z, acc.z); acc.w = fmaf(w0, v0.w, acc.w);
    }
    const float4 bb = ((const float4*)b)[lane];
    float r0 = fmaxf(fmaf(di, acc.x, bb.x), 0.0f);
    float r1 = fmaxf(fmaf(di, acc.y, bb.y), 0.0f);
    float r2 = fmaxf(fmaf(di, acc.z, bb.z), 0.0f);
    float r3 = fmaxf(fmaf(di, acc.w, bb.w), 0.0f);
    __half h0 = __float2half_rn(r0), h1 = __float2half_rn(r1);
    __half h2 = __float2half_rn(r2), h3 = __float2half_rn(r3);
    __half l0 = __float2half_rn(r0 - __half2float(h0));
    __half l1 = __float2half_rn(r1 - __half2float(h1));
    __half l2 = __float2half_rn(r2 - __half2float(h2));
    __half l3 = __float2half_rn(r3 - __half2float(h3));
    int off = node * Hh + lane * 4;
    *(__half2*)(g_hi + off)     = __halves2half2(h0, h1);
    *(__half2*)(g_hi + off + 2) = __halves2half2(h2, h3);
    *(__half2*)(g_lo + off)     = __halves2half2(l0, l1);
    *(__half2*)(g_lo + off + 2) = __halves2half2(l2, l3);
}

// ---------------- split-fp16 tensor-core GEMM ----------------
// D[N,256] = A[N,K] @ B[K,256] computed as Ahi*Bhi + Alo*Bhi + Ahi*Blo.
// Tiles: BM=128, BN=128, BK=32. 256 threads = 8 warps, warp tile 64x32.
// smem padded row stride 40 halfs (conflict-free fragment loads).
#define MMA16816(d, a, b)                                                     \
    asm volatile(                                                             \
        "mma.sync.aligned.m16n8k16.row.col.f32.f16.f16.f32 "                  \
        "{%0,%1,%2,%3},{%4,%5,%6,%7},{%8,%9},{%0,%1,%2,%3};"                  \
        : "+f"(d[0]), "+f"(d[1]), "+f"(d[2]), "+f"(d[3])                      \
        : "r"(a[0]), "r"(a[1]), "r"(a[2]), "r"(a[3]), "r"(b[0]), "r"(b[1]))

template <int K, bool RELU>
__global__ __launch_bounds__(256, 1) void gemm_kernel(int widx, const float* __restrict__ bias) {
    const __half* __restrict__ Ahi = (K == Ff) ? g_xhi : g_hi;
    const __half* __restrict__ Alo = (K == Ff) ? g_xlo : g_lo;
    const __half* __restrict__ Bhi = (K == Ff) ? g_w1hiT : g_whiT + widx * (Hh * Hh);
    const __half* __restrict__ Blo = (K == Ff) ? g_w1loT : g_wloT + widx * (Hh * Hh);

    __shared__ __half sAhi[128 * 40];
    __shared__ __half sAlo[128 * 40];
    __shared__ __half sBhi[128 * 40];
    __shared__ __half sBlo[128 * 40];

    const int tid = threadIdx.x;
    const int warp = tid >> 5;
    const int lane = tid & 31;
    const int g = lane >> 2;
    const int t = lane & 3;
    const int wm = warp >> 2;   // 0..1
    const int wn = warp & 3;    // 0..3
    const int rowbase = blockIdx.y * 128;
    const int colbase = blockIdx.x * 128;

    // global->smem mapping
    const int lrow = tid >> 1;
    const int lch = tid & 1;
    int arow = rowbase + lrow;
    if (arow > Nn - 1) arow = Nn - 1;
    const __half* pAhi = Ahi + arow * K + lch * 16;
    const __half* pAlo = Alo + arow * K + lch * 16;
    const __half* pBhi = Bhi + (colbase + lrow) * K + lch * 16;
    const __half* pBlo = Blo + (colbase + lrow) * K + lch * 16;
    const int sidx = lrow * 40 + lch * 16;

    float acc[4][4][4];
    #pragma unroll
    for (int a = 0; a < 4; a++)
        #pragma unroll
        for (int bq = 0; bq < 4; bq++)
            #pragma unroll
            for (int c = 0; c < 4; c++) acc[a][bq][c] = 0.0f;

    uint4 rAh0, rAh1, rAl0, rAl1, rBh0, rBh1, rBl0, rBl1;
    // prefetch tile 0
    rAh0 = *(const uint4*)(pAhi);     rAh1 = *(const uint4*)(pAhi + 8);
    rAl0 = *(const uint4*)(pAlo);     rAl1 = *(const uint4*)(pAlo + 8);
    rBh0 = *(const uint4*)(pBhi);     rBh1 = *(const uint4*)(pBhi + 8);
    rBl0 = *(const uint4*)(pBlo);     rBl1 = *(const uint4*)(pBlo + 8);

    const int NT = K / 32;
    #pragma unroll 1
    for (int kt = 0; kt < NT; kt++) {
        // store prefetched tile
        *(uint2*)&sAhi[sidx]      = make_uint2(rAh0.x, rAh0.y);
        *(uint2*)&sAhi[sidx + 4]  = make_uint2(rAh0.z, rAh0.w);
        *(uint2*)&sAhi[sidx + 8]  = make_uint2(rAh1.x, rAh1.y);
        *(uint2*)&sAhi[sidx + 12] = make_uint2(rAh1.z, rAh1.w);
        *(uint2*)&sAlo[sidx]      = make_uint2(rAl0.x, rAl0.y);
        *(uint2*)&sAlo[sidx + 4]  = make_uint2(rAl0.z, rAl0.w);
        *(uint2*)&sAlo[sidx + 8]  = make_uint2(rAl1.x, rAl1.y);
        *(uint2*)&sAlo[sidx + 12] = make_uint2(rAl1.z, rAl1.w);
        *(uint2*)&sBhi[sidx]      = make_uint2(rBh0.x, rBh0.y);
        *(uint2*)&sBhi[sidx + 4]  = make_uint2(rBh0.z, rBh0.w);
        *(uint2*)&sBhi[sidx + 8]  = make_uint2(rBh1.x, rBh1.y);
        *(uint2*)&sBhi[sidx + 12] = make_uint2(rBh1.z, rBh1.w);
        *(uint2*)&sBlo[sidx]      = make_uint2(rBl0.x, rBl0.y);
        *(uint2*)&sBlo[sidx + 4]  = make_uint2(rBl0.z, rBl0.w);
        *(uint2*)&sBlo[sidx + 8]  = make_uint2(rBl1.x, rBl1.y);
        *(uint2*)&sBlo[sidx + 12] = make_uint2(rBl1.z, rBl1.w);
        __syncthreads();

        if (kt + 1 < NT) {
            int k0 = (kt + 1) * 32;
            rAh0 = *(const uint4*)(pAhi + k0);     rAh1 = *(const uint4*)(pAhi + k0 + 8);
            rAl0 = *(const uint4*)(pAlo + k0);     rAl1 = *(const uint4*)(pAlo + k0 + 8);
            rBh0 = *(const uint4*)(pBhi + k0);     rBh1 = *(const uint4*)(pBhi + k0 + 8);
            rBl0 = *(const uint4*)(pBlo + k0);     rBl1 = *(const uint4*)(pBlo + k0 + 8);
        }

        #pragma unroll
        for (int kh = 0; kh < 32; kh += 16) {
            uint32_t Ah[4][4], Al[4][4], Bh[4][2], Bl[4][2];
            #pragma unroll
            for (int im = 0; im < 4; im++) {
                int mb = (wm * 64 + im * 16 + g) * 40 + kh + 2 * t;
                Ah[im][0] = *(const uint32_t*)&sAhi[mb];
                Ah[im][1] = *(const uint32_t*)&sAhi[mb + 8 * 40];
                Ah[im][2] = *(const uint32_t*)&sAhi[mb + 8];
                Ah[im][3] = *(const uint32_t*)&sAhi[mb + 8 * 40 + 8];
                Al[im][0] = *(const uint32_t*)&sAlo[mb];
                Al[im][1] = *(const uint32_t*)&sAlo[mb + 8 * 40];
                Al[im][2] = *(const uint32_t*)&sAlo[mb + 8];
                Al[im][3] = *(const uint32_t*)&sAlo[mb + 8 * 40 + 8];
            }
            #pragma unroll
            for (int in = 0; in < 4; in++) {
                int nb = (wn * 32 + in * 8 + g) * 40 + kh + 2 * t;
                Bh[in][0] = *(const uint32_t*)&sBhi[nb];
                Bh[in][1] = *(const uint32_t*)&sBhi[nb + 8];
                Bl[in][0] = *(const uint32_t*)&sBlo[nb];
                Bl[in][1] = *(const uint32_t*)&sBlo[nb + 8];
            }
            #pragma unroll
            for (int im = 0; im < 4; im++)
                #pragma unroll
                for (int in = 0; in < 4; in++) {
                    MMA16816(acc[im][in], Ah[im], Bh[in]);
                    MMA16816(acc[im][in], Al[im], Bh[in]);
                    MMA16816(acc[im][in], Ah[im], Bl[in]);
                }
        }
        __syncthreads();
    }

    // epilogue
    #pragma unroll
    for (int im = 0; im < 4; im++) {
        int m0 = rowbase + wm * 64 + im * 16 + g;
        #pragma unroll
        for (int in = 0; in < 4; in++) {
            int n = colbase + wn * 32 + in * 8 + 2 * t;
            float c0 = acc[im][in][0], c1 = acc[im][in][1];
            float c2 = acc[im][in][2], c3 = acc[im][in][3];
            if (RELU) {
                float bb0 = bias[n], bb1 = bias[n + 1];
                if (m0 < Nn) {
                    float r0 = fmaxf(c0 + bb0, 0.0f), r1 = fmaxf(c1 + bb1, 0.0f);
                    __half h0 = __float2half_rn(r0), h1 = __float2half_rn(r1);
                    __half l0 = __float2half_rn(r0 - __half2float(h0));
                    __half l1 = __float2half_rn(r1 - __half2float(h1));
                    *(__half2*)(g_hi + m0 * Hh + n) = __halves2half2(h0, h1);
                    *(__half2*)(g_lo + m0 * Hh + n) = __halves2half2(l0, l1);
                }
                if (m0 + 8 < Nn) {
                    float r2 = fmaxf(c2 + bb0, 0.0f), r3 = fmaxf(c3 + bb1, 0.0f);
                    __half h2 = __float2half_rn(r2), h3 = __float2half_rn(r3);
                    __half l2 = __float2half_rn(r2 - __half2float(h2));
                    __half l3 = __float2half_rn(r3 - __half2float(h3));
                    *(__half2*)(g_hi + (m0 + 8) * Hh + n) = __halves2half2(h2, h3);
                    *(__half2*)(g_lo + (m0 + 8) * Hh + n) = __halves2half2(l2, l3);
                }
            } else {
                if (m0 < Nn) {
                    float2 v; v.x = c0; v.y = c1;
                    *(float2*)(g_z + m0 * Hh + n) = v;
                }
                if (m0 + 8 < Nn) {
                    float2 v; v.x = c2; v.y = c3;
                    *(float2*)(g_z + (m0 + 8) * Hh + n) = v;
                }
            }
        }
    }
}

// ---------------- pooling ----------------
__global__ void pool_kernel(const int* __restrict__ batch) {
    int i = blockIdx.x;
    int f = threadIdx.x;
    int gph = batch[i];
    float v = __half2float(g_hi[i * Hh + f]) + __half2float(g_lo[i * Hh + f]);
    atomicAdd(&g_pool[gph * Hh + f], v);
    if (f == 0) atomicAdd(&g_pcnt[gph], 1);
}

// ---------------- output head ----------------
__global__ void out_kernel(const float* __restrict__ Wout,
                           const float* __restrict__ bout,
                           float* __restrict__ out) {
    __shared__ float sh[Hh];
    int g = blockIdx.x;
    int f = threadIdx.x;
    int c = g_pcnt[g];
    float inv = 1.0f / fmaxf((float)c, 1.0f);
    sh[f] = g_pool[g * Hh + f] * inv;
    __syncthreads();
    if (f < Cc) {
        float a = bout[f];
        for (int k = 0; k < Hh; k++)
            a = fmaf(sh[k], Wout[k * Cc + f], a);
        out[g * Cc + f] = a;
    }
}

// ---------------- launch ----------------
extern "C" void kernel_launch(void* const* d_in, const int* in_sizes, int n_in,
                              void* d_out, int out_size) {
    const float* x     = (const float*)d_in[0];
    const int*   ei    = (const int*)d_in[1];
    const int*   batch = (const int*)d_in[2];
    const float* W1 = (const float*)d_in[3];
    const float* b1 = (const float*)d_in[4];
    const float* W2 = (const float*)d_in[5];
    const float* b2 = (const float*)d_in[6];
    const float* W3 = (const float*)d_in[7];
    const float* b3 = (const float*)d_in[8];
    const float* W4 = (const float*)d_in[9];
    const float* b4 = (const float*)d_in[10];
    const float* W5 = (const float*)d_in[11];
    const float* b5 = (const float*)d_in[12];
    const float* Wout = (const float*)d_in[13];
    const float* bout = (const float*)d_in[14];
    float* out = (float*)d_out;

    int eblocks = (Ee + 255) / 256;
    dim3 ggrid(Hh / 128, (Nn + 127) / 128);   // (2, 157)

    init_kernel<<<(Nn + 255) / 256, 256>>>();
    deg_kernel<<<eblocks, 256>>>(ei);
    scan_kernel<<<1, SCAN_T>>>();
    scatter_kernel<<<eblocks, 256>>>(ei);

    // weight prep (split + transpose)
    wprep_kernel<<<(Ff * Hh + 255) / 256, 256>>>(W1, -1, Ff);
    wprep_kernel<<<(Hh * Hh + 255) / 256, 256>>>(W2, 0, Hh);
    wprep_kernel<<<(Hh * Hh + 255) / 256, 256>>>(W3, 1, Hh);
    wprep_kernel<<<(Hh * Hh + 255) / 256, 256>>>(W4, 2, Hh);
    wprep_kernel<<<(Hh * Hh + 255) / 256, 256>>>(W5, 3, Hh);

    // layer 1: aggregate x first (A(XW) = (AX)W), then GEMM with bias+relu
    aggx_kernel<<<Nn / 16, 256>>>(x);
    gemm_kernel<Ff, true><<<ggrid, 256>>>(0, b1);

    // layers 2..5: GEMM -> aggregate(+bias+relu)
    gemm_kernel<Hh, false><<<ggrid, 256>>>(0, nullptr);
    agg_kernel<<<Nn / 4, 256>>>(b2);
    gemm_kernel<Hh, false><<<ggrid, 256>>>(1, nullptr);
    agg_kernel<<<Nn / 4, 256>>>(b3);
    gemm_kernel<Hh, false><<<ggrid, 256>>>(2, nullptr);
    agg_kernel<<<Nn / 4, 256>>>(b4);
    gemm_kernel<Hh, false><<<ggrid, 256>>>(3, nullptr);
    agg_kernel<<<Nn / 4, 256>>>(b5);

    pool_kernel<<<Nn, 256>>>(batch);
    out_kernel<<<Gg, 256>>>(Wout, bout, out);
}

// round 3
// speedup vs baseline: 1.7027x; 1.0053x over previous
#include <cuda_runtime.h>
#include <cuda_fp16.h>
#include <math.h>
#include <stdint.h>

#define Nn 20000
#define Ee 320000
#define Ff 64
#define Hh 256
#define Cc 10
#define Gg 64

// ---------------- device scratch (static, no allocation) ----------------
__device__ float  g_z[Nn * Hh];          // GEMM output (pre-aggregation), fp32
__device__ __half g_hi[Nn * Hh];         // hidden state hi (fp16)
__device__ __half g_lo[Nn * Hh];         // hidden state lo (fp16)
__device__ __half g_xhi[Nn * Ff];        // aggregated X hi
__device__ __half g_xlo[Nn * Ff];        // aggregated X lo
__device__ __half g_whiT[4 * Hh * Hh];   // W2..W5 transposed [m][k], hi
__device__ __half g_wloT[4 * Hh * Hh];   // W2..W5 transposed [m][k], lo
__device__ __half g_w1hiT[Hh * Ff];      // W1 transposed [m=256][k=64]
__device__ __half g_w1loT[Hh * Ff];

__device__ float g_dinv[Nn];
__device__ int   g_cnt[Nn];
__device__ int   g_off[Nn + 1];
__device__ int   g_cur[Nn];
__device__ int   g_csr[Ee];
__device__ float g_pool[Gg * Hh];
__device__ int   g_pcnt[Gg];

// ---------------- init ----------------
__global__ void init_kernel() {
    int idx = blockIdx.x * blockDim.x + threadIdx.x;
    if (idx < Nn) g_cnt[idx] = 0;
    if (idx < Gg * Hh) g_pool[idx] = 0.0f;
    if (idx < Gg) g_pcnt[idx] = 0;
}

// ---------------- degree count (edges) + per-graph node count ----------------
__global__ void deg_kernel(const int* __restrict__ edge_index,
                           const int* __restrict__ batch) {
    int e = blockIdx.x * blockDim.x + threadIdx.x;
    if (e < Ee) {
        atomicAdd(&g_cnt[edge_index[Ee + e]], 1);
    } else if (e < Ee + Nn) {
        atomicAdd(&g_pcnt[batch[e - Ee]], 1);
    }
}

// ---------------- single-block scan ----------------
#define SCAN_T 1024
#define SCAN_CH ((Nn + SCAN_T - 1) / SCAN_T)
__global__ void scan_kernel() {
    __shared__ int sh[SCAN_T];
    int t = threadIdx.x;
    int base = t * SCAN_CH;
    int s = 0;
    #pragma unroll
    for (int i = 0; i < SCAN_CH; i++) {
        int idx = base + i;
        if (idx < Nn) s += g_cnt[idx];
    }
    sh[t] = s;
    __syncthreads();
    for (int d = 1; d < SCAN_T; d <<= 1) {
        int v = (t >= d) ? sh[t - d] : 0;
        __syncthreads();
        sh[t] += v;
        __syncthreads();
    }
    int run = (t == 0) ? 0 : sh[t - 1];
    for (int i = 0; i < SCAN_CH; i++) {
        int idx = base + i;
        if (idx < Nn) {
            int c = g_cnt[idx];
            g_off[idx] = run;
            g_cur[idx] = run;
            g_dinv[idx] = rsqrtf((float)(c + 1));
            run += c;
        }
    }
    if (t == SCAN_T - 1) g_off[Nn] = sh[SCAN_T - 1];
}

// ---------------- scatter into dest-sorted CSR ----------------
__global__ void scatter_kernel(const int* __restrict__ edge_index) {
    int e = blockIdx.x * blockDim.x + threadIdx.x;
    if (e < Ee) {
        int r = edge_index[e];
        int c = edge_index[Ee + e];
        g_csr[atomicAdd(&g_cur[c], 1)] = r;
    }
}

// ---------------- weight prep (all 5 weights in one launch) ----------------
__global__ void wprep_kernel(const float* __restrict__ W1,
                             const float* __restrict__ W2,
                             const float* __restrict__ W3,
                             const float* __restrict__ W4,
                             const float* __restrict__ W5) {
    int idx = blockIdx.x * blockDim.x + threadIdx.x;
    if (idx < Ff * Hh) {
        int m = idx / Ff, k = idx - m * Ff;
        float v = W1[k * Hh + m];
        __half hi = __float2half_rn(v);
        g_w1hiT[idx] = hi;
        g_w1loT[idx] = __float2half_rn(v - __half2float(hi));
        return;
    }
    int r = idx - Ff * Hh;
    if (r >= 4 * Hh * Hh) return;
    int widx = r >> 16;            // / 65536
    int loc = r & 65535;
    int m = loc >> 8, k = loc & 255;
    const float* W = (widx == 0) ? W2 : (widx == 1) ? W3 : (widx == 2) ? W4 : W5;
    float v = W[k * Hh + m];
    __half hi = __float2half_rn(v);
    g_whiT[r] = hi;
    g_wloT[r] = __float2half_rn(v - __half2float(hi));
}

// ---------------- aggregate raw X (F=64), write fp16 hi/lo ----------------
__global__ void aggx_kernel(const float* __restrict__ x) {
    int tid = threadIdx.x;
    int node = blockIdx.x * 16 + (tid >> 4);
    int lane = tid & 15;
    float di = g_dinv[node];
    const float4* x4 = (const float4*)x;
    float4 self = x4[node * 16 + lane];
    float4 acc;
    acc.x = di * self.x; acc.y = di * self.y; acc.z = di * self.z; acc.w = di * self.w;
    int s = g_off[node], e = g_off[node + 1];
    int k = s;
    for (; k + 2 <= e; k += 2) {
        int j0 = g_csr[k], j1 = g_csr[k + 1];
        float w0 = g_dinv[j0], w1 = g_dinv[j1];
        float4 v0 = x4[j0 * 16 + lane];
        float4 v1 = x4[j1 * 16 + lane];
        acc.x = fmaf(w0, v0.x, acc.x); acc.y = fmaf(w0, v0.y, acc.y);
        acc.z = fmaf(w0, v0.z, acc.z); acc.w = fmaf(w0, v0.w, acc.w);
        acc.x = fmaf(w1, v1.x, acc.x); acc.y = fmaf(w1, v1.y, acc.y);
        acc.z = fmaf(w1, v1.z, acc.z); acc.w = fmaf(w1, v1.w, acc.w);
    }
    if (k < e) {
        int j0 = g_csr[k];
        float w0 = g_dinv[j0];
        float4 v0 = x4[j0 * 16 + lane];
        acc.x = fmaf(w0, v0.x, acc.x); acc.y = fmaf(w0, v0.y, acc.y);
        acc.z = fmaf(w0, v0.z, acc.z); acc.w = fmaf(w0, v0.w, acc.w);
    }
    float r0 = di * acc.x, r1 = di * acc.y, r2 = di * acc.z, r3 = di * acc.w;
    __half h0 = __float2half_rn(r0), h1 = __float2half_rn(r1);
    __half h2 = __float2half_rn(r2), h3 = __float2half_rn(r3);
    __half l0 = __float2half_rn(r0 - __half2float(h0));
    __half l1 = __float2half_rn(r1 - __half2float(h1));
    __half l2 = __float2half_rn(r2 - __half2float(h2));
    __half l3 = __float2half_rn(r3 - __half2float(h3));
    int off = node * Ff + lane * 4;
    *(__half2*)(g_xhi + off)     = __halves2half2(h0, h1);
    *(__half2*)(g_xhi + off + 2) = __halves2half2(h2, h3);
    *(__half2*)(g_xlo + off)     = __halves2half2(l0, l1);
    *(__half2*)(g_xlo + off + 2) = __halves2half2(l2, l3);
}

// ---------------- aggregation core (layers 2..5) ----------------
// Computes r = relu( dinv_i*(dinv_i*z_i + sum_j dinv_j*z_j) + b ) for 4 feats.
// POOL=false: store hi/lo fp16 for next GEMM. POOL=true: atomicAdd into g_pool.
template <bool POOL>
__global__ void agg_kernel(const float* __restrict__ b, const int* __restrict__ batch) {
    int tid = threadIdx.x;
    int node = blockIdx.x * 4 + (tid >> 6);
    int lane = tid & 63;
    float di = g_dinv[node];
    const float4* z4 = (const float4*)g_z;
    float4 self = z4[node * 64 + lane];
    float4 acc;
    acc.x = di * self.x; acc.y = di * self.y; acc.z = di * self.z; acc.w = di * self.w;
    int s = g_off[node], e = g_off[node + 1];
    int k = s;
    for (; k + 2 <= e; k += 2) {
        int j0 = g_csr[k], j1 = g_csr[k + 1];
        float w0 = g_dinv[j0], w1 = g_dinv[j1];
        float4 v0 = z4[j0 * 64 + lane];
        float4 v1 = z4[j1 * 64 + lane];
        acc.x = fmaf(w0, v0.x, acc.x); acc.y = fmaf(w0, v0.y, acc.y);
        acc.z = fmaf(w0, v0.z, acc.z); acc.w = fmaf(w0, v0.w, acc.w);
        acc.x = fmaf(w1, v1.x, acc.x); acc.y = fmaf(w1, v1.y, acc.y);
        acc.z = fmaf(w1, v1.z, acc.z); acc.w = fmaf(w1, v1.w, acc.w);
    }
    if (k < e) {
        int j0 = g_csr[k];
        float w0 = g_dinv[j0];
        float4 v0 = z4[j0 * 64 + lane];
        acc.x = fmaf(w0, v0.x, acc.x); acc.y = fmaf(w0, v0.y, acc.y);
        acc.z = fmaf(w0, v0.z, acc.z); acc.w = fmaf(w0, v0.w, acc.w);
    }
    const float4 bb = ((const float4*)b)[lane];
    float r0 = fmaxf(fmaf(di, acc.x, bb.x), 0.0f);
    float r1 = fmaxf(fmaf(di, acc.y, bb.y), 0.0f);
    float r2 = fmaxf(fmaf(di, acc.z, bb.z), 0.0f);
    float r3 = fmaxf(fmaf(di, acc.w, bb.w), 0.0f);
    if (POOL) {
        int gph = batch[node];
        float* p = g_pool + gph * Hh + lane * 4;
        atomicAdd(p + 0, r0);
        atomicAdd(p + 1, r1);
        atomicAdd(p + 2, r2);
        atomicAdd(p + 3, r3);
    } else {
        __half h0 = __float2half_rn(r0), h1 = __float2half_rn(r1);
        __half h2 = __float2half_rn(r2), h3 = __float2half_rn(r3);
        __half l0 = __float2half_rn(r0 - __half2float(h0));
        __half l1 = __float2half_rn(r1 - __half2float(h1));
        __half l2 = __float2half_rn(r2 - __half2float(h2));
        __half l3 = __float2half_rn(r3 - __half2float(h3));
        int off = node * Hh + lane * 4;
        *(__half2*)(g_hi + off)     = __halves2half2(h0, h1);
        *(__half2*)(g_hi + off + 2) = __halves2half2(h2, h3);
        *(__half2*)(g_lo + off)     = __halves2half2(l0, l1);
        *(__half2*)(g_lo + off + 2) = __halves2half2(l2, l3);
    }
}

// ---------------- split-fp16 tensor-core GEMM (cp.async double-buffered) ----
// D[N,256] = A[N,K] @ B[K,256] as Ahi*Bhi + Alo*Bhi + Ahi*Blo.
// BM=128, BN=128, BK=32, 256 threads (8 warps, warp tile 64x32), 2 CTA/SM.
#define MMA16816(d, a, b)                                                     \
    asm volatile(                                                             \
        "mma.sync.aligned.m16n8k16.row.col.f32.f16.f16.f32 "                  \
        "{%0,%1,%2,%3},{%4,%5,%6,%7},{%8,%9},{%0,%1,%2,%3};"                  \
        : "+f"(d[0]), "+f"(d[1]), "+f"(d[2]), "+f"(d[3])                      \
        : "r"(a[0]), "r"(a[1]), "r"(a[2]), "r"(a[3]), "r"(b[0]), "r"(b[1]))

__device__ __forceinline__ void cp16(uint32_t dst, const void* src) {
    asm volatile("cp.async.cg.shared.global [%0], [%1], 16;" :: "r"(dst), "l"(src));
}
__device__ __forceinline__ void cp_commit() {
    asm volatile("cp.async.commit_group;");
}
template <int NWait>
__device__ __forceinline__ void cp_wait() {
    asm volatile("cp.async.wait_group %0;" :: "n"(NWait));
}

// per-buffer layout (in halfs): sAhi[5120] sAlo[5120] sBhi[5120] sBlo[5120]
#define TILE_H 5120
#define BUF_H  (4 * TILE_H)

template <int K, bool RELU>
__global__ __launch_bounds__(256, 2) void gemm_kernel(int widx, const float* __restrict__ bias) {
    const __half* __restrict__ Ahi = (K == Ff) ? g_xhi : g_hi;
    const __half* __restrict__ Alo = (K == Ff) ? g_xlo : g_lo;
    const __half* __restrict__ Bhi = (K == Ff) ? g_w1hiT : g_whiT + widx * (Hh * Hh);
    const __half* __restrict__ Blo = (K == Ff) ? g_w1loT : g_wloT + widx * (Hh * Hh);

    extern __shared__ __half sh[];
    const uint32_t sh32 = (uint32_t)__cvta_generic_to_shared(sh);

    const int tid = threadIdx.x;
    const int warp = tid >> 5;
    const int lane = tid & 31;
    const int g = lane >> 2;
    const int t = lane & 3;
    const int wm = warp >> 2;   // 0..1
    const int wn = warp & 3;    // 0..3
    const int rowbase = blockIdx.y * 128;
    const int colbase = blockIdx.x * 128;

    const int lrow = tid >> 1;
    const int lch = tid & 1;
    int arow = rowbase + lrow;
    if (arow > Nn - 1) arow = Nn - 1;
    const __half* pAhi = Ahi + arow * K + lch * 16;
    const __half* pAlo = Alo + arow * K + lch * 16;
    const __half* pBhi = Bhi + (colbase + lrow) * K + lch * 16;
    const __half* pBlo = Blo + (colbase + lrow) * K + lch * 16;
    const uint32_t sidx_b = (uint32_t)(lrow * 40 + lch * 16) * 2;  // byte offset in tile

    float acc[4][4][4];
    #pragma unroll
    for (int a = 0; a < 4; a++)
        #pragma unroll
        for (int bq = 0; bq < 4; bq++)
            #pragma unroll
            for (int c = 0; c < 4; c++) acc[a][bq][c] = 0.0f;

    const int NT = K / 32;

    // issue tile kt into buffer buf
    auto issue = [&](int kt, int buf) {
        int k0 = kt * 32;
        uint32_t base = sh32 + (uint32_t)buf * (BUF_H * 2) + sidx_b;
        cp16(base,                     pAhi + k0);
        cp16(base + 16,                pAhi + k0 + 8);
        cp16(base + TILE_H * 2,        pAlo + k0);
        cp16(base + TILE_H * 2 + 16,   pAlo + k0 + 8);
        cp16(base + TILE_H * 4,        pBhi + k0);
        cp16(base + TILE_H * 4 + 16,   pBhi + k0 + 8);
        cp16(base + TILE_H * 6,        pBlo + k0);
        cp16(base + TILE_H * 6 + 16,   pBlo + k0 + 8);
    };

    issue(0, 0);
    cp_commit();

    #pragma unroll 1
    for (int kt = 0; kt < NT; kt++) {
        int buf = kt & 1;
        if (kt + 1 < NT) {
            issue(kt + 1, buf ^ 1);
            cp_commit();
            cp_wait<1>();
        } else {
            cp_wait<0>();
        }
        __syncthreads();

        const __half* sAhi = sh + buf * BUF_H;
        const __half* sAlo = sAhi + TILE_H;
        const __half* sBhi = sAhi + 2 * TILE_H;
        const __half* sBlo = sAhi + 3 * TILE_H;

        #pragma unroll
        for (int kh = 0; kh < 32; kh += 16) {
            uint32_t Ah[4][4], Al[4][4], Bh[4][2], Bl[4][2];
            #pragma unroll
            for (int im = 0; im < 4; im++) {
                int mb = (wm * 64 + im * 16 + g) * 40 + kh + 2 * t;
                Ah[im][0] = *(const uint32_t*)&sAhi[mb];
                Ah[im][1] = *(const uint32_t*)&sAhi[mb + 8 * 40];
                Ah[im][2] = *(const uint32_t*)&sAhi[mb + 8];
                Ah[im][3] = *(const uint32_t*)&sAhi[mb + 8 * 40 + 8];
                Al[im][0] = *(const uint32_t*)&sAlo[mb];
                Al[im][1] = *(const uint32_t*)&sAlo[mb + 8 * 40];
                Al[im][2] = *(const uint32_t*)&sAlo[mb + 8];
                Al[im][3] = *(const uint32_t*)&sAlo[mb + 8 * 40 + 8];
            }
            #pragma unroll
            for (int in = 0; in < 4; in++) {
                int nb = (wn * 32 + in * 8 + g) * 40 + kh + 2 * t;
                Bh[in][0] = *(const uint32_t*)&sBhi[nb];
                Bh[in][1] = *(const uint32_t*)&sBhi[nb + 8];
                Bl[in][0] = *(const uint32_t*)&sBlo[nb];
                Bl[in][1] = *(const uint32_t*)&sBlo[nb + 8];
            }
            #pragma unroll
            for (int im = 0; im < 4; im++)
                #pragma unroll
                for (int in = 0; in < 4; in++) {
                    MMA16816(acc[im][in], Ah[im], Bh[in]);
                    MMA16816(acc[im][in], Al[im], Bh[in]);
                    MMA16816(acc[im][in], Ah[im], Bl[in]);
                }
        }
        __syncthreads();
    }

    // epilogue
    #pragma unroll
    for (int im = 0; im < 4; im++) {
        int m0 = rowbase + wm * 64 + im * 16 + g;
        #pragma unroll
        for (int in = 0; in < 4; in++) {
            int n = colbase + wn * 32 + in * 8 + 2 * t;
            float c0 = acc[im][in][0], c1 = acc[im][in][1];
            float c2 = acc[im][in][2], c3 = acc[im][in][3];
            if (RELU) {
                float bb0 = bias[n], bb1 = bias[n + 1];
                if (m0 < Nn) {
                    float r0 = fmaxf(c0 + bb0, 0.0f), r1 = fmaxf(c1 + bb1, 0.0f);
                    __half h0 = __float2half_rn(r0), h1 = __float2half_rn(r1);
                    __half l0 = __float2half_rn(r0 - __half2float(h0));
                    __half l1 = __float2half_rn(r1 - __half2float(h1));
                    *(__half2*)(g_hi + m0 * Hh + n) = __halves2half2(h0, h1);
                    *(__half2*)(g_lo + m0 * Hh + n) = __halves2half2(l0, l1);
                }
                if (m0 + 8 < Nn) {
                    float r2 = fmaxf(c2 + bb0, 0.0f), r3 = fmaxf(c3 + bb1, 0.0f);
                    __half h2 = __float2half_rn(r2), h3 = __float2half_rn(r3);
                    __half l2 = __float2half_rn(r2 - __half2float(h2));
                    __half l3 = __float2half_rn(r3 - __half2float(h3));
                    *(__half2*)(g_hi + (m0 + 8) * Hh + n) = __halves2half2(h2, h3);
                    *(__half2*)(g_lo + (m0 + 8) * Hh + n) = __halves2half2(l2, l3);
                }
            } else {
                if (m0 < Nn) {
                    float2 v; v.x = c0; v.y = c1;
                    *(float2*)(g_z + m0 * Hh + n) = v;
                }
                if (m0 + 8 < Nn) {
                    float2 v; v.x = c2; v.y = c3;
                    *(float2*)(g_z + (m0 + 8) * Hh + n) = v;
                }
            }
        }
    }
}

// ---------------- output head ----------------
__global__ void out_kernel(const float* __restrict__ Wout,
                           const float* __restrict__ bout,
                           float* __restrict__ out) {
    __shared__ float sh[Hh];
    int g = blockIdx.x;
    int f = threadIdx.x;
    int c = g_pcnt[g];
    float inv = 1.0f / fmaxf((float)c, 1.0f);
    sh[f] = g_pool[g * Hh + f] * inv;
    __syncthreads();
    if (f < Cc) {
        float a = bout[f];
        for (int k = 0; k < Hh; k++)
            a = fmaf(sh[k], Wout[k * Cc + f], a);
        out[g * Cc + f] = a;
    }
}

// ---------------- launch ----------------
extern "C" void kernel_launch(void* const* d_in, const int* in_sizes, int n_in,
                              void* d_out, int out_size) {
    const float* x     = (const float*)d_in[0];
    const int*   ei    = (const int*)d_in[1];
    const int*   batch = (const int*)d_in[2];
    const float* W1 = (const float*)d_in[3];
    const float* b1 = (const float*)d_in[4];
    const float* W2 = (const float*)d_in[5];
    const float* b2 = (const float*)d_in[6];
    const float* W3 = (const float*)d_in[7];
    const float* b3 = (const float*)d_in[8];
    const float* W4 = (const float*)d_in[9];
    const float* b4 = (const float*)d_in[10];
    const float* W5 = (const float*)d_in[11];
    const float* b5 = (const float*)d_in[12];
    const float* Wout = (const float*)d_in[13];
    const float* bout = (const float*)d_in[14];
    float* out = (float*)d_out;

    const int SMEM_BYTES = 2 * BUF_H * 2;   // 81920
    static bool attr_set = false;
    if (!attr_set) {
        cudaFuncSetAttribute(gemm_kernel<Ff, true>,
                             cudaFuncAttributeMaxDynamicSharedMemorySize, SMEM_BYTES);
        cudaFuncSetAttribute(gemm_kernel<Hh, false>,
                             cudaFuncAttributeMaxDynamicSharedMemorySize, SMEM_BYTES);
        attr_set = true;
    }

    int eblocks = (Ee + 255) / 256;
    int dblocks = (Ee + Nn + 255) / 256;
    dim3 ggrid(Hh / 128, (Nn + 127) / 128);   // (2, 157)

    init_kernel<<<(Nn + 255) / 256, 256>>>();
    deg_kernel<<<dblocks, 256>>>(ei, batch);
    scan_kernel<<<1, SCAN_T>>>();
    scatter_kernel<<<eblocks, 256>>>(ei);
    wprep_kernel<<<(Ff * Hh + 4 * Hh * Hh + 255) / 256, 256>>>(W1, W2, W3, W4, W5);

    // layer 1: aggregate x first (A(XW) = (AX)W), then GEMM with bias+relu
    aggx_kernel<<<Nn / 16, 256>>>(x);
    gemm_kernel<Ff, true><<<ggrid, 256, SMEM_BYTES>>>(0, b1);

    // layers 2..5
    gemm_kernel<Hh, false><<<ggrid, 256, SMEM_BYTES>>>(0, nullptr);
    agg_kernel<false><<<Nn / 4, 256>>>(b2, batch);
    gemm_kernel<Hh, false><<<ggrid, 256, SMEM_BYTES>>>(1, nullptr);
    agg_kernel<false><<<Nn / 4, 256>>>(b3, batch);
    gemm_kernel<Hh, false><<<ggrid, 256, SMEM_BYTES>>>(2, nullptr);
    agg_kernel<false><<<Nn / 4, 256>>>(b4, batch);
    gemm_kernel<Hh, false><<<ggrid, 256, SMEM_BYTES>>>(3, nullptr);
    agg_kernel<true><<<Nn / 4, 256>>>(b5, batch);   // fused pool

    out_kernel<<<Gg, 256>>>(Wout, bout, out);
}